// round 14
// baseline (speedup 1.0000x reference)
#include <cuda_runtime.h>
#include <cuda_fp16.h>
#include <math.h>
#include <stdint.h>

#define N_NODES 50000
#define FEAT    128
#define MAX_E   800000
#define SCAN_TILE 4096
#define SCAN_NT ((N_NODES + SCAN_TILE - 1) / SCAN_TILE)   // 13

// ---- scratch (static __device__ arrays; no runtime allocation) ----
__device__ __half g_bufT[N_NODES * FEAT];   // post-GEMM features (fp16)
__device__ __half g_bufH[N_NODES * FEAT];   // post-agg features (fp16)
__device__ __half g_xh[N_NODES * FEAT];     // fp16 copy of input x
__device__ int   g_deg[N_NODES];
__device__ float g_dis[N_NODES];
__device__ int   g_rowoff[N_NODES + 1];
__device__ int   g_rank[MAX_E];             // per-edge rank within its dst list
__device__ int4  g_csr4[MAX_E / 2];         // (src,dis) pairs, 16B aligned
__device__ unsigned long long g_tilestate[SCAN_NT];

// ================= GEMM pieces =================
#define WROW 72

__device__ __forceinline__ uint32_t pack_h2(__half a, __half b) {
    __half2 h = __halves2half2(a, b);
    return *(uint32_t*)&h;
}
__device__ __forceinline__ void mma_f16(float* c, const uint32_t* a, uint32_t b0, uint32_t b1) {
    asm volatile(
        "mma.sync.aligned.m16n8k16.row.col.f32.f16.f16.f32 "
        "{%0,%1,%2,%3}, {%4,%5,%6,%7}, {%8,%9}, {%0,%1,%2,%3};"
        : "+f"(c[0]), "+f"(c[1]), "+f"(c[2]), "+f"(c[3])
        : "r"(a[0]), "r"(a[1]), "r"(a[2]), "r"(a[3]), "r"(b0), "r"(b1));
}
__device__ __forceinline__ void stage_W(uint32_t* Wh, const float* __restrict__ W, int tid) {
    for (int idx = tid; idx < 64 * 128; idx += 256) {
        int p = idx >> 7, n = idx & 127;
        int k = p * 2;
        float w0 = W[k * FEAT + n];
        float w1 = W[(k + 1) * FEAT + n];
        int kstep = p >> 3, q = p & 7;
        int word = n * WROW + kstep * 8 + (q & 3) * 2 + (q >> 2);
        Wh[word] = pack_h2(__float2half_rn(w0), __float2half_rn(w1));
    }
}

__device__ __forceinline__ void gemm_body(uint32_t* Wh, const __half* __restrict__ A,
                                          const float* __restrict__ W,
                                          __half* __restrict__ C, int nrows, int tile) {
    int tid = threadIdx.x, wid = tid >> 5, lane = tid & 31;
    int g = lane >> 2, t = lane & 3;
    stage_W(Wh, W, tid);
    __syncthreads();

    int r0 = tile * 128 + wid * 16 + g;
    int r1 = r0 + 8;
    bool v0 = r0 < nrows, v1 = r1 < nrows;

    float acc[16][4];
    #pragma unroll
    for (int n0 = 0; n0 < 16; n0++)
        #pragma unroll
        for (int j = 0; j < 4; j++) acc[n0][j] = 0.0f;

    #pragma unroll
    for (int kstep = 0; kstep < 8; kstep++) {
        int ka = kstep * 16 + 2 * t;
        uint32_t a[4];
        a[0] = v0 ? *(const uint32_t*)&A[r0 * FEAT + ka]     : 0u;
        a[1] = v1 ? *(const uint32_t*)&A[r1 * FEAT + ka]     : 0u;
        a[2] = v0 ? *(const uint32_t*)&A[r0 * FEAT + ka + 8] : 0u;
        a[3] = v1 ? *(const uint32_t*)&A[r1 * FEAT + ka + 8] : 0u;

        int bword = g * WROW + kstep * 8 + t * 2;
        #pragma unroll
        for (int n0 = 0; n0 < 16; n0++) {
            uint2 bh = *(const uint2*)&Wh[n0 * 8 * WROW + bword];
            mma_f16(acc[n0], a, bh.x, bh.y);
        }
    }

    #pragma unroll
    for (int n0 = 0; n0 < 16; n0++) {
        int col = n0 * 8 + 2 * t;
        if (v0) *(__half2*)&C[r0 * FEAT + col] = __floats2half2_rn(acc[n0][0], acc[n0][1]);
        if (v1) *(__half2*)&C[r1 * FEAT + col] = __floats2half2_rn(acc[n0][2], acc[n0][3]);
    }
}

// ================= setup bodies =================
__device__ __forceinline__ void count_body(const int* __restrict__ dst, int E, int bid) {
    int i = (bid * 256 + threadIdx.x) * 8;
    if (i + 7 < E) {
        int4 d0 = *(const int4*)&dst[i];
        int4 d1 = *(const int4*)&dst[i + 4];
        int4 r0, r1;
        r0.x = atomicAdd(&g_deg[d0.x], 1);
        r0.y = atomicAdd(&g_deg[d0.y], 1);
        r0.z = atomicAdd(&g_deg[d0.z], 1);
        r0.w = atomicAdd(&g_deg[d0.w], 1);
        r1.x = atomicAdd(&g_deg[d1.x], 1);
        r1.y = atomicAdd(&g_deg[d1.y], 1);
        r1.z = atomicAdd(&g_deg[d1.z], 1);
        r1.w = atomicAdd(&g_deg[d1.w], 1);
        *(int4*)&g_rank[i]     = r0;
        *(int4*)&g_rank[i + 4] = r1;
    } else {
        for (int j = i; j < E; j++) g_rank[j] = atomicAdd(&g_deg[dst[j]], 1);
    }
}

__device__ __forceinline__ void x2h_body(const float* __restrict__ x, __half* __restrict__ xh,
                                         int n, int bid) {
    int i = (bid * 256 + threadIdx.x) * 8;
    if (i + 7 < n) {
        float4 f0 = *(const float4*)&x[i];
        float4 f1 = *(const float4*)&x[i + 4];
        uint4 o;
        __half2 h0 = __floats2half2_rn(f0.x, f0.y);
        __half2 h1 = __floats2half2_rn(f0.z, f0.w);
        __half2 h2 = __floats2half2_rn(f1.x, f1.y);
        __half2 h3 = __floats2half2_rn(f1.z, f1.w);
        o.x = *(uint32_t*)&h0; o.y = *(uint32_t*)&h1;
        o.z = *(uint32_t*)&h2; o.w = *(uint32_t*)&h3;
        *(uint4*)&xh[i] = o;
    }
}

__device__ __forceinline__ void fill_body(const int* __restrict__ src,
                                          const int* __restrict__ dst, int E, int bid) {
    int2* csr2 = (int2*)g_csr4;
    int i = (bid * 256 + threadIdx.x) * 8;
    if (i + 7 < E) {
        int4 s0 = *(const int4*)&src[i];
        int4 s1 = *(const int4*)&src[i + 4];
        int4 d0 = *(const int4*)&dst[i];
        int4 d1 = *(const int4*)&dst[i + 4];
        int4 r0 = *(const int4*)&g_rank[i];
        int4 r1 = *(const int4*)&g_rank[i + 4];
        float f0 = g_dis[s0.x], f1 = g_dis[s0.y], f2 = g_dis[s0.z], f3 = g_dis[s0.w];
        float f4 = g_dis[s1.x], f5 = g_dis[s1.y], f6 = g_dis[s1.z], f7 = g_dis[s1.w];
        csr2[g_rowoff[d0.x] + r0.x] = make_int2(s0.x, __float_as_int(f0));
        csr2[g_rowoff[d0.y] + r0.y] = make_int2(s0.y, __float_as_int(f1));
        csr2[g_rowoff[d0.z] + r0.z] = make_int2(s0.z, __float_as_int(f2));
        csr2[g_rowoff[d0.w] + r0.w] = make_int2(s0.w, __float_as_int(f3));
        csr2[g_rowoff[d1.x] + r1.x] = make_int2(s1.x, __float_as_int(f4));
        csr2[g_rowoff[d1.y] + r1.y] = make_int2(s1.y, __float_as_int(f5));
        csr2[g_rowoff[d1.z] + r1.z] = make_int2(s1.z, __float_as_int(f6));
        csr2[g_rowoff[d1.w] + r1.w] = make_int2(s1.w, __float_as_int(f7));
    } else {
        for (int j = i; j < E; j++) {
            int sj = src[j];
            csr2[g_rowoff[dst[j]] + g_rank[j]] = make_int2(sj, __float_as_int(g_dis[sj]));
        }
    }
}

// ================= merged kernels =================
__global__ __launch_bounds__(256) void k_setup1(const int* __restrict__ dst, int E,
                                                const float* __restrict__ x,
                                                __half* __restrict__ xh, int n, int nCount) {
    int bid = blockIdx.x;
    if (bid < nCount) count_body(dst, E, bid);
    else              x2h_body(x, xh, n, bid - nCount);
}

__global__ __launch_bounds__(256) void k_fillgemm1(const int* __restrict__ src,
                                                   const int* __restrict__ dst, int E,
                                                   const __half* __restrict__ A,
                                                   const float* __restrict__ W,
                                                   __half* __restrict__ C,
                                                   int nrows, int ntiles) {
    __shared__ uint32_t Wh[128 * WROW];
    int bid = blockIdx.x;
    if (bid < ntiles) gemm_body(Wh, A, W, C, nrows, bid);
    else              fill_body(src, dst, E, bid - ntiles);
}

__global__ __launch_bounds__(256) void k_gemm_h(const __half* __restrict__ A,
                                                const float* __restrict__ W,
                                                __half* __restrict__ C, int nrows) {
    __shared__ uint32_t Wh[128 * WROW];
    gemm_body(Wh, A, W, C, nrows, blockIdx.x);
}

// ================= scan =================
__global__ __launch_bounds__(1024) void k_scan_dl() {
    __shared__ int sh_w[32];
    __shared__ unsigned int sh_prefix;
    int tid = threadIdx.x, lane = tid & 31, wid = tid >> 5;
    int tile = blockIdx.x;
    int i0 = tile * SCAN_TILE + tid * 4;

    int4 v = make_int4(0, 0, 0, 0);
    if (i0 < N_NODES) {
        v = *(const int4*)&g_deg[i0];
        float4 d;
        d.x = rsqrtf((float)(v.x + 1));
        d.y = rsqrtf((float)(v.y + 1));
        d.z = rsqrtf((float)(v.z + 1));
        d.w = rsqrtf((float)(v.w + 1));
        *(float4*)&g_dis[i0] = d;
    }
    int t0 = v.x, t1 = t0 + v.y, t2 = t1 + v.z, t3 = t2 + v.w;
    int sc = t3;
    #pragma unroll
    for (int d = 1; d < 32; d <<= 1) {
        int t = __shfl_up_sync(0xffffffffu, sc, d);
        if (lane >= d) sc += t;
    }
    if (lane == 31) sh_w[wid] = sc;
    __syncthreads();
    if (wid == 0) {
        int ws = sh_w[lane];
        #pragma unroll
        for (int d = 1; d < 32; d <<= 1) {
            int t = __shfl_up_sync(0xffffffffu, ws, d);
            if (lane >= d) ws += t;
        }
        sh_w[lane] = ws;
    }
    __syncthreads();
    int total = sh_w[31];
    int thr_excl = (wid ? sh_w[wid - 1] : 0) + sc - t3;

    if (tid == 0) {
        unsigned long long st = ((tile == 0) ? (2ULL << 32) : (1ULL << 32)) | (unsigned)total;
        atomicExch(&g_tilestate[tile], st);
    }
    if (wid == 0) {
        unsigned int prefix = 0;
        if (tile > 0) {
            bool have = lane < tile;
            unsigned long long s = 0;
            if (have) {
                do { s = *(volatile unsigned long long*)&g_tilestate[tile - 1 - lane]; }
                while ((unsigned)(s >> 32) == 0u);
            }
            unsigned flag = (unsigned)(s >> 32);
            unsigned mask = __ballot_sync(0xffffffffu, have && flag == 2u);
            int firstInc = __ffs(mask) - 1;   // exists: tile 0 is always INCLUSIVE
            unsigned contrib = (have && lane <= firstInc) ? (unsigned)s : 0u;
            #pragma unroll
            for (int d = 16; d; d >>= 1) contrib += __shfl_xor_sync(0xffffffffu, contrib, d);
            prefix = contrib;
            if (lane == 0)
                atomicExch(&g_tilestate[tile], (2ULL << 32) | (unsigned)(prefix + (unsigned)total));
        }
        if (lane == 0) sh_prefix = prefix;
    }
    __syncthreads();
    int base = (int)sh_prefix + thr_excl;
    if (i0 < N_NODES) {
        int4 o = make_int4(base, base + t0, base + t1, base + t2);
        *(int4*)&g_rowoff[i0] = o;
    }
    if (tile == SCAN_NT - 1 && tid == 0) g_rowoff[N_NODES] = (int)sh_prefix + total;
}

// ================= aggregation v3: int4 CSR + software pipeline =========
__device__ __forceinline__ float elu1(float v) { return v > 0.0f ? v : expm1f(v); }

__device__ __forceinline__ uint2 ld_row_u(const __half* __restrict__ Tl, int s) {
    return *(const uint2*)(Tl + s * FEAT);
}
__device__ __forceinline__ void acc_row(float4& acc, uint2 u, float w) {
    __half2 h0 = *(__half2*)&u.x;
    __half2 h1 = *(__half2*)&u.y;
    float2 f0 = __half22float2(h0);
    float2 f1 = __half22float2(h1);
    acc.x = fmaf(w, f0.x, acc.x);
    acc.y = fmaf(w, f0.y, acc.y);
    acc.z = fmaf(w, f1.x, acc.z);
    acc.w = fmaf(w, f1.y, acc.w);
}

template<int FUSE_FINAL>
__global__ __launch_bounds__(256) void k_agg_t(const __half* __restrict__ T,
                                               const float* __restrict__ bias,
                                               __half* __restrict__ Hout,
                                               const float* __restrict__ Wl,
                                               const float* __restrict__ bl,
                                               float* __restrict__ out) {
    const int2* __restrict__ csr2 = (const int2*)g_csr4;
    int warp = (int)((blockIdx.x * blockDim.x + threadIdx.x) >> 5);
    int lane = threadIdx.x & 31;
    if (warp >= N_NODES) return;
    int node = warp;
    float dd = g_dis[node];
    const __half* Tl = T + lane * 4;

    float4 acc;
    {
        uint2 u = ld_row_u(Tl, node);
        __half2 h0 = *(__half2*)&u.x;
        __half2 h1 = *(__half2*)&u.y;
        float2 f0 = __half22float2(h0);
        float2 f1 = __half22float2(h1);
        float ws = dd * dd;
        acc = make_float4(ws * f0.x, ws * f0.y, ws * f1.x, ws * f1.y);
    }

    int e   = g_rowoff[node];
    int end = g_rowoff[node + 1];

    if (e < end && (e & 1)) {           // align to int4 boundary
        int2 p = csr2[e];
        acc_row(acc, ld_row_u(Tl, p.x), __int_as_float(p.y) * dd);
        e++;
    }

    int n4 = (end - e) >> 2;            // groups of 4 edges
    if (n4 > 0) {
        const int4* cp = (const int4*)&csr2[e];
        int4 pa = cp[0], pb = cp[1];
        uint2 r0 = ld_row_u(Tl, pa.x);
        uint2 r1 = ld_row_u(Tl, pa.z);
        uint2 r2 = ld_row_u(Tl, pb.x);
        uint2 r3 = ld_row_u(Tl, pb.z);
        for (int i = 1; i < n4; i++) {
            int4 qa = cp[2 * i], qb = cp[2 * i + 1];     // next group loads first
            uint2 s0 = ld_row_u(Tl, qa.x);
            uint2 s1 = ld_row_u(Tl, qa.z);
            uint2 s2 = ld_row_u(Tl, qb.x);
            uint2 s3 = ld_row_u(Tl, qb.z);
            acc_row(acc, r0, __int_as_float(pa.y) * dd); // current group math
            acc_row(acc, r1, __int_as_float(pa.w) * dd);
            acc_row(acc, r2, __int_as_float(pb.y) * dd);
            acc_row(acc, r3, __int_as_float(pb.w) * dd);
            pa = qa; pb = qb;
            r0 = s0; r1 = s1; r2 = s2; r3 = s3;
        }
        acc_row(acc, r0, __int_as_float(pa.y) * dd);
        acc_row(acc, r1, __int_as_float(pa.w) * dd);
        acc_row(acc, r2, __int_as_float(pb.y) * dd);
        acc_row(acc, r3, __int_as_float(pb.w) * dd);
        e += n4 * 4;
    }
    for (; e < end; e++) {              // tail 0-3 edges
        int2 p = csr2[e];
        acc_row(acc, ld_row_u(Tl, p.x), __int_as_float(p.y) * dd);
    }

    float4 b = *(const float4*)&bias[lane * 4];
    float4 r;
    r.x = elu1(acc.x + b.x);
    r.y = elu1(acc.y + b.y);
    r.z = elu1(acc.z + b.z);
    r.w = elu1(acc.w + b.w);

    if (FUSE_FINAL) {
        float4 w = *(const float4*)&Wl[lane * 4];
        float s = r.x * w.x + r.y * w.y + r.z * w.z + r.w * w.w;
        #pragma unroll
        for (int d = 16; d; d >>= 1) s += __shfl_xor_sync(0xffffffffu, s, d);
        if (lane == 0) out[node] = s + bl[0];
    } else {
        uint2 st;
        __half2 h0 = __floats2half2_rn(r.x, r.y);
        __half2 h1 = __floats2half2_rn(r.z, r.w);
        st.x = *(uint32_t*)&h0;
        st.y = *(uint32_t*)&h1;
        *(uint2*)&Hout[node * FEAT + lane * 4] = st;
    }
}

// ================= launch =================
extern "C" void kernel_launch(void* const* d_in, const int* in_sizes, int n_in,
                              void* d_out, int out_size) {
    const float* x  = (const float*)d_in[0];
    const float* Ws = (const float*)d_in[1];
    const float* bs = (const float*)d_in[2];
    const float* Wl = (const float*)d_in[3];
    const float* bl = (const float*)d_in[4];
    const int*   ei = (const int*)d_in[5];
    const int E = in_sizes[5] / 2;
    const int* src = ei;
    const int* dst = ei + E;
    float* out = (float*)d_out;

    __half *hbuf = nullptr, *tbuf = nullptr, *xh = nullptr;
    void *degp = nullptr, *tsp = nullptr;
    cudaGetSymbolAddress((void**)&hbuf, g_bufH);
    cudaGetSymbolAddress((void**)&tbuf, g_bufT);
    cudaGetSymbolAddress((void**)&xh, g_xh);
    cudaGetSymbolAddress(&degp, g_deg);
    cudaGetSymbolAddress(&tsp, g_tilestate);

    cudaMemsetAsync(degp, 0, N_NODES * sizeof(int), 0);
    cudaMemsetAsync(tsp, 0, SCAN_NT * sizeof(unsigned long long), 0);

    const int nX = N_NODES * FEAT;
    const int nCount = (E / 8 + 255) / 256;          // 391
    const int nX2h   = (nX / 8 + 255) / 256;         // 3125
    const int ntiles = (N_NODES + 127) / 128;        // 391
    const int nFill  = (E / 8 + 255) / 256;          // 391
    const int nagg   = (N_NODES + 7) / 8;

    k_setup1<<<nCount + nX2h, 256>>>(dst, E, x, xh, nX, nCount);
    k_scan_dl<<<SCAN_NT, 1024>>>();
    k_fillgemm1<<<ntiles + nFill, 256>>>(src, dst, E, xh, Ws, tbuf, N_NODES, ntiles);
    k_agg_t<0><<<nagg, 256>>>(tbuf, bs, hbuf, nullptr, nullptr, nullptr);
    k_gemm_h<<<ntiles, 256>>>(hbuf, Ws + FEAT * FEAT, tbuf, N_NODES);
    k_agg_t<0><<<nagg, 256>>>(tbuf, bs + FEAT, hbuf, nullptr, nullptr, nullptr);
    k_gemm_h<<<ntiles, 256>>>(hbuf, Ws + 2 * FEAT * FEAT, tbuf, N_NODES);
    k_agg_t<1><<<nagg, 256>>>(tbuf, bs + 2 * FEAT, nullptr, Wl, bl, out);
}

// round 15
// speedup vs baseline: 1.0753x; 1.0753x over previous
#include <cuda_runtime.h>
#include <cuda_fp16.h>
#include <math.h>
#include <stdint.h>

#define N_NODES 50000
#define FEAT    128
#define MAX_E   800000
#define SCAN_TILE 4096
#define SCAN_NT ((N_NODES + SCAN_TILE - 1) / SCAN_TILE)   // 13

// ---- scratch (static __device__ arrays; no runtime allocation) ----
__device__ __half g_bufT[N_NODES * FEAT];   // post-GEMM features (fp16)
__device__ __half g_bufH[N_NODES * FEAT];   // post-agg features (fp16)
__device__ __half g_xh[N_NODES * FEAT];     // fp16 copy of input x
__device__ int   g_deg[N_NODES];
__device__ float g_dis[N_NODES];
__device__ int   g_rowoff[N_NODES + 1];
__device__ int   g_rank[MAX_E];             // per-edge rank within its dst list
__device__ int4  g_csr4[MAX_E / 2];         // (row_byte_off, dis) pairs, 16B aligned
__device__ unsigned long long g_tilestate[SCAN_NT];

// ================= GEMM pieces =================
#define WROW 72

__device__ __forceinline__ uint32_t pack_h2(__half a, __half b) {
    __half2 h = __halves2half2(a, b);
    return *(uint32_t*)&h;
}
__device__ __forceinline__ void mma_f16(float* c, const uint32_t* a, uint32_t b0, uint32_t b1) {
    asm volatile(
        "mma.sync.aligned.m16n8k16.row.col.f32.f16.f16.f32 "
        "{%0,%1,%2,%3}, {%4,%5,%6,%7}, {%8,%9}, {%0,%1,%2,%3};"
        : "+f"(c[0]), "+f"(c[1]), "+f"(c[2]), "+f"(c[3])
        : "r"(a[0]), "r"(a[1]), "r"(a[2]), "r"(a[3]), "r"(b0), "r"(b1));
}
__device__ __forceinline__ void stage_W(uint32_t* Wh, const float* __restrict__ W, int tid) {
    for (int idx = tid; idx < 64 * 128; idx += 256) {
        int p = idx >> 7, n = idx & 127;
        int k = p * 2;
        float w0 = W[k * FEAT + n];
        float w1 = W[(k + 1) * FEAT + n];
        int kstep = p >> 3, q = p & 7;
        int word = n * WROW + kstep * 8 + (q & 3) * 2 + (q >> 2);
        Wh[word] = pack_h2(__float2half_rn(w0), __float2half_rn(w1));
    }
}

__device__ __forceinline__ void gemm_body(uint32_t* Wh, const __half* __restrict__ A,
                                          const float* __restrict__ W,
                                          __half* __restrict__ C, int nrows, int tile) {
    int tid = threadIdx.x, wid = tid >> 5, lane = tid & 31;
    int g = lane >> 2, t = lane & 3;
    stage_W(Wh, W, tid);
    __syncthreads();

    int r0 = tile * 128 + wid * 16 + g;
    int r1 = r0 + 8;
    bool v0 = r0 < nrows, v1 = r1 < nrows;

    float acc[16][4];
    #pragma unroll
    for (int n0 = 0; n0 < 16; n0++)
        #pragma unroll
        for (int j = 0; j < 4; j++) acc[n0][j] = 0.0f;

    #pragma unroll
    for (int kstep = 0; kstep < 8; kstep++) {
        int ka = kstep * 16 + 2 * t;
        uint32_t a[4];
        a[0] = v0 ? *(const uint32_t*)&A[r0 * FEAT + ka]     : 0u;
        a[1] = v1 ? *(const uint32_t*)&A[r1 * FEAT + ka]     : 0u;
        a[2] = v0 ? *(const uint32_t*)&A[r0 * FEAT + ka + 8] : 0u;
        a[3] = v1 ? *(const uint32_t*)&A[r1 * FEAT + ka + 8] : 0u;

        int bword = g * WROW + kstep * 8 + t * 2;
        #pragma unroll
        for (int n0 = 0; n0 < 16; n0++) {
            uint2 bh = *(const uint2*)&Wh[n0 * 8 * WROW + bword];
            mma_f16(acc[n0], a, bh.x, bh.y);
        }
    }

    #pragma unroll
    for (int n0 = 0; n0 < 16; n0++) {
        int col = n0 * 8 + 2 * t;
        if (v0) *(__half2*)&C[r0 * FEAT + col] = __floats2half2_rn(acc[n0][0], acc[n0][1]);
        if (v1) *(__half2*)&C[r1 * FEAT + col] = __floats2half2_rn(acc[n0][2], acc[n0][3]);
    }
}

// ================= setup bodies =================
__device__ __forceinline__ void count_body(const int* __restrict__ dst, int E, int bid) {
    int i = (bid * 256 + threadIdx.x) * 8;
    if (i + 7 < E) {
        int4 d0 = *(const int4*)&dst[i];
        int4 d1 = *(const int4*)&dst[i + 4];
        int4 r0, r1;
        r0.x = atomicAdd(&g_deg[d0.x], 1);
        r0.y = atomicAdd(&g_deg[d0.y], 1);
        r0.z = atomicAdd(&g_deg[d0.z], 1);
        r0.w = atomicAdd(&g_deg[d0.w], 1);
        r1.x = atomicAdd(&g_deg[d1.x], 1);
        r1.y = atomicAdd(&g_deg[d1.y], 1);
        r1.z = atomicAdd(&g_deg[d1.z], 1);
        r1.w = atomicAdd(&g_deg[d1.w], 1);
        *(int4*)&g_rank[i]     = r0;
        *(int4*)&g_rank[i + 4] = r1;
    } else {
        for (int j = i; j < E; j++) g_rank[j] = atomicAdd(&g_deg[dst[j]], 1);
    }
}

__device__ __forceinline__ void x2h_body(const float* __restrict__ x, __half* __restrict__ xh,
                                         int n, int bid) {
    int i = (bid * 256 + threadIdx.x) * 8;
    if (i + 7 < n) {
        float4 f0 = *(const float4*)&x[i];
        float4 f1 = *(const float4*)&x[i + 4];
        uint4 o;
        __half2 h0 = __floats2half2_rn(f0.x, f0.y);
        __half2 h1 = __floats2half2_rn(f0.z, f0.w);
        __half2 h2 = __floats2half2_rn(f1.x, f1.y);
        __half2 h3 = __floats2half2_rn(f1.z, f1.w);
        o.x = *(uint32_t*)&h0; o.y = *(uint32_t*)&h1;
        o.z = *(uint32_t*)&h2; o.w = *(uint32_t*)&h3;
        *(uint4*)&xh[i] = o;
    }
}

// fill: store (row byte offset = src*FEAT*2, dis[src]) — no atomics
__device__ __forceinline__ void fill_body(const int* __restrict__ src,
                                          const int* __restrict__ dst, int E, int bid) {
    int2* csr2 = (int2*)g_csr4;
    int i = (bid * 256 + threadIdx.x) * 8;
    if (i + 7 < E) {
        int4 s0 = *(const int4*)&src[i];
        int4 s1 = *(const int4*)&src[i + 4];
        int4 d0 = *(const int4*)&dst[i];
        int4 d1 = *(const int4*)&dst[i + 4];
        int4 r0 = *(const int4*)&g_rank[i];
        int4 r1 = *(const int4*)&g_rank[i + 4];
        float f0 = g_dis[s0.x], f1 = g_dis[s0.y], f2 = g_dis[s0.z], f3 = g_dis[s0.w];
        float f4 = g_dis[s1.x], f5 = g_dis[s1.y], f6 = g_dis[s1.z], f7 = g_dis[s1.w];
        csr2[g_rowoff[d0.x] + r0.x] = make_int2(s0.x * 256, __float_as_int(f0));
        csr2[g_rowoff[d0.y] + r0.y] = make_int2(s0.y * 256, __float_as_int(f1));
        csr2[g_rowoff[d0.z] + r0.z] = make_int2(s0.z * 256, __float_as_int(f2));
        csr2[g_rowoff[d0.w] + r0.w] = make_int2(s0.w * 256, __float_as_int(f3));
        csr2[g_rowoff[d1.x] + r1.x] = make_int2(s1.x * 256, __float_as_int(f4));
        csr2[g_rowoff[d1.y] + r1.y] = make_int2(s1.y * 256, __float_as_int(f5));
        csr2[g_rowoff[d1.z] + r1.z] = make_int2(s1.z * 256, __float_as_int(f6));
        csr2[g_rowoff[d1.w] + r1.w] = make_int2(s1.w * 256, __float_as_int(f7));
    } else {
        for (int j = i; j < E; j++) {
            int sj = src[j];
            csr2[g_rowoff[dst[j]] + g_rank[j]] = make_int2(sj * 256, __float_as_int(g_dis[sj]));
        }
    }
}

// ================= merged kernels =================
__global__ __launch_bounds__(256) void k_setup1(const int* __restrict__ dst, int E,
                                                const float* __restrict__ x,
                                                __half* __restrict__ xh, int n, int nCount) {
    int bid = blockIdx.x;
    if (bid < nCount) count_body(dst, E, bid);
    else              x2h_body(x, xh, n, bid - nCount);
}

__global__ __launch_bounds__(256) void k_fillgemm1(const int* __restrict__ src,
                                                   const int* __restrict__ dst, int E,
                                                   const __half* __restrict__ A,
                                                   const float* __restrict__ W,
                                                   __half* __restrict__ C,
                                                   int nrows, int ntiles) {
    __shared__ uint32_t Wh[128 * WROW];
    int bid = blockIdx.x;
    if (bid < ntiles) gemm_body(Wh, A, W, C, nrows, bid);
    else              fill_body(src, dst, E, bid - ntiles);
}

__global__ __launch_bounds__(256) void k_gemm_h(const __half* __restrict__ A,
                                                const float* __restrict__ W,
                                                __half* __restrict__ C, int nrows) {
    __shared__ uint32_t Wh[128 * WROW];
    gemm_body(Wh, A, W, C, nrows, blockIdx.x);
}

// ================= scan =================
__global__ __launch_bounds__(1024) void k_scan_dl() {
    __shared__ int sh_w[32];
    __shared__ unsigned int sh_prefix;
    int tid = threadIdx.x, lane = tid & 31, wid = tid >> 5;
    int tile = blockIdx.x;
    int i0 = tile * SCAN_TILE + tid * 4;

    int4 v = make_int4(0, 0, 0, 0);
    if (i0 < N_NODES) {
        v = *(const int4*)&g_deg[i0];
        float4 d;
        d.x = rsqrtf((float)(v.x + 1));
        d.y = rsqrtf((float)(v.y + 1));
        d.z = rsqrtf((float)(v.z + 1));
        d.w = rsqrtf((float)(v.w + 1));
        *(float4*)&g_dis[i0] = d;
    }
    int t0 = v.x, t1 = t0 + v.y, t2 = t1 + v.z, t3 = t2 + v.w;
    int sc = t3;
    #pragma unroll
    for (int d = 1; d < 32; d <<= 1) {
        int t = __shfl_up_sync(0xffffffffu, sc, d);
        if (lane >= d) sc += t;
    }
    if (lane == 31) sh_w[wid] = sc;
    __syncthreads();
    if (wid == 0) {
        int ws = sh_w[lane];
        #pragma unroll
        for (int d = 1; d < 32; d <<= 1) {
            int t = __shfl_up_sync(0xffffffffu, ws, d);
            if (lane >= d) ws += t;
        }
        sh_w[lane] = ws;
    }
    __syncthreads();
    int total = sh_w[31];
    int thr_excl = (wid ? sh_w[wid - 1] : 0) + sc - t3;

    if (tid == 0) {
        unsigned long long st = ((tile == 0) ? (2ULL << 32) : (1ULL << 32)) | (unsigned)total;
        atomicExch(&g_tilestate[tile], st);
    }
    if (wid == 0) {
        unsigned int prefix = 0;
        if (tile > 0) {
            bool have = lane < tile;
            unsigned long long s = 0;
            if (have) {
                do { s = *(volatile unsigned long long*)&g_tilestate[tile - 1 - lane]; }
                while ((unsigned)(s >> 32) == 0u);
            }
            unsigned flag = (unsigned)(s >> 32);
            unsigned mask = __ballot_sync(0xffffffffu, have && flag == 2u);
            int firstInc = __ffs(mask) - 1;   // exists: tile 0 is always INCLUSIVE
            unsigned contrib = (have && lane <= firstInc) ? (unsigned)s : 0u;
            #pragma unroll
            for (int d = 16; d; d >>= 1) contrib += __shfl_xor_sync(0xffffffffu, contrib, d);
            prefix = contrib;
            if (lane == 0)
                atomicExch(&g_tilestate[tile], (2ULL << 32) | (unsigned)(prefix + (unsigned)total));
        }
        if (lane == 0) sh_prefix = prefix;
    }
    __syncthreads();
    int base = (int)sh_prefix + thr_excl;
    if (i0 < N_NODES) {
        int4 o = make_int4(base, base + t0, base + t1, base + t2);
        *(int4*)&g_rowoff[i0] = o;
    }
    if (tile == SCAN_NT - 1 && tid == 0) g_rowoff[N_NODES] = (int)sh_prefix + total;
}

// ================= aggregation v4: premult offsets + int4 CSR, flat loop ==
__device__ __forceinline__ float elu1(float v) { return v > 0.0f ? v : expm1f(v); }

__device__ __forceinline__ uint2 ld_row_off(const char* __restrict__ Tl, int off) {
    return *(const uint2*)(Tl + off);
}
__device__ __forceinline__ void acc_row(float4& acc, uint2 u, float w) {
    __half2 h0 = *(__half2*)&u.x;
    __half2 h1 = *(__half2*)&u.y;
    float2 f0 = __half22float2(h0);
    float2 f1 = __half22float2(h1);
    acc.x = fmaf(w, f0.x, acc.x);
    acc.y = fmaf(w, f0.y, acc.y);
    acc.z = fmaf(w, f1.x, acc.z);
    acc.w = fmaf(w, f1.y, acc.w);
}

template<int FUSE_FINAL>
__global__ __launch_bounds__(256) void k_agg_t(const __half* __restrict__ T,
                                               const float* __restrict__ bias,
                                               __half* __restrict__ Hout,
                                               const float* __restrict__ Wl,
                                               const float* __restrict__ bl,
                                               float* __restrict__ out) {
    const int2* __restrict__ csr2 = (const int2*)g_csr4;
    int warp = (int)((blockIdx.x * blockDim.x + threadIdx.x) >> 5);
    int lane = threadIdx.x & 31;
    if (warp >= N_NODES) return;
    int node = warp;
    float dd = g_dis[node];
    const char* Tl = (const char*)(T + lane * 4);   // lane's column base

    float4 acc;
    {
        uint2 u = ld_row_off(Tl, node * 256);
        __half2 h0 = *(__half2*)&u.x;
        __half2 h1 = *(__half2*)&u.y;
        float2 f0 = __half22float2(h0);
        float2 f1 = __half22float2(h1);
        float ws = dd * dd;
        acc = make_float4(ws * f0.x, ws * f0.y, ws * f1.x, ws * f1.y);
    }

    int e   = g_rowoff[node];
    int end = g_rowoff[node + 1];

    if (e < end && (e & 1)) {           // align to int4 boundary
        int2 p = csr2[e];
        acc_row(acc, ld_row_off(Tl, p.x), __int_as_float(p.y) * dd);
        e++;
    }
    for (; e + 3 < end; e += 4) {       // 4 edges: 2 LDG.128 csr + 4 row LDG
        int4 pa = *(const int4*)&csr2[e];
        int4 pb = *(const int4*)&csr2[e + 2];
        uint2 r0 = ld_row_off(Tl, pa.x);
        uint2 r1 = ld_row_off(Tl, pa.z);
        uint2 r2 = ld_row_off(Tl, pb.x);
        uint2 r3 = ld_row_off(Tl, pb.z);
        acc_row(acc, r0, __int_as_float(pa.y) * dd);
        acc_row(acc, r1, __int_as_float(pa.w) * dd);
        acc_row(acc, r2, __int_as_float(pb.y) * dd);
        acc_row(acc, r3, __int_as_float(pb.w) * dd);
    }
    for (; e < end; e++) {              // tail 0-3 edges
        int2 p = csr2[e];
        acc_row(acc, ld_row_off(Tl, p.x), __int_as_float(p.y) * dd);
    }

    float4 b = *(const float4*)&bias[lane * 4];
    float4 r;
    r.x = elu1(acc.x + b.x);
    r.y = elu1(acc.y + b.y);
    r.z = elu1(acc.z + b.z);
    r.w = elu1(acc.w + b.w);

    if (FUSE_FINAL) {
        float4 w = *(const float4*)&Wl[lane * 4];
        float s = r.x * w.x + r.y * w.y + r.z * w.z + r.w * w.w;
        #pragma unroll
        for (int d = 16; d; d >>= 1) s += __shfl_xor_sync(0xffffffffu, s, d);
        if (lane == 0) out[node] = s + bl[0];
    } else {
        uint2 st;
        __half2 h0 = __floats2half2_rn(r.x, r.y);
        __half2 h1 = __floats2half2_rn(r.z, r.w);
        st.x = *(uint32_t*)&h0;
        st.y = *(uint32_t*)&h1;
        *(uint2*)&Hout[node * FEAT + lane * 4] = st;
    }
}

// ================= launch =================
extern "C" void kernel_launch(void* const* d_in, const int* in_sizes, int n_in,
                              void* d_out, int out_size) {
    const float* x  = (const float*)d_in[0];
    const float* Ws = (const float*)d_in[1];
    const float* bs = (const float*)d_in[2];
    const float* Wl = (const float*)d_in[3];
    const float* bl = (const float*)d_in[4];
    const int*   ei = (const int*)d_in[5];
    const int E = in_sizes[5] / 2;
    const int* src = ei;
    const int* dst = ei + E;
    float* out = (float*)d_out;

    __half *hbuf = nullptr, *tbuf = nullptr, *xh = nullptr;
    void *degp = nullptr, *tsp = nullptr;
    cudaGetSymbolAddress((void**)&hbuf, g_bufH);
    cudaGetSymbolAddress((void**)&tbuf, g_bufT);
    cudaGetSymbolAddress((void**)&xh, g_xh);
    cudaGetSymbolAddress(&degp, g_deg);
    cudaGetSymbolAddress(&tsp, g_tilestate);

    cudaMemsetAsync(degp, 0, N_NODES * sizeof(int), 0);
    cudaMemsetAsync(tsp, 0, SCAN_NT * sizeof(unsigned long long), 0);

    const int nX = N_NODES * FEAT;
    const int nCount = (E / 8 + 255) / 256;          // 391
    const int nX2h   = (nX / 8 + 255) / 256;         // 3125
    const int ntiles = (N_NODES + 127) / 128;        // 391
    const int nFill  = (E / 8 + 255) / 256;          // 391
    const int nagg   = (N_NODES + 7) / 8;

    k_setup1<<<nCount + nX2h, 256>>>(dst, E, x, xh, nX, nCount);
    k_scan_dl<<<SCAN_NT, 1024>>>();
    k_fillgemm1<<<ntiles + nFill, 256>>>(src, dst, E, xh, Ws, tbuf, N_NODES, ntiles);
    k_agg_t<0><<<nagg, 256>>>(tbuf, bs, hbuf, nullptr, nullptr, nullptr);
    k_gemm_h<<<ntiles, 256>>>(hbuf, Ws + FEAT * FEAT, tbuf, N_NODES);
    k_agg_t<0><<<nagg, 256>>>(tbuf, bs + FEAT, hbuf, nullptr, nullptr, nullptr);
    k_gemm_h<<<ntiles, 256>>>(hbuf, Ws + 2 * FEAT * FEAT, tbuf, N_NODES);
    k_agg_t<1><<<nagg, 256>>>(tbuf, bs + 2 * FEAT, nullptr, Wl, bl, out);
}

// round 16
// speedup vs baseline: 1.2652x; 1.1766x over previous
#include <cuda_runtime.h>
#include <cuda_fp16.h>
#include <math.h>
#include <stdint.h>

#define N_NODES 50000
#define FEAT    128
#define MAX_E   800000
#define SCAN_TILE 4096
#define SCAN_NT ((N_NODES + SCAN_TILE - 1) / SCAN_TILE)   // 13

// ---- scratch (static __device__ arrays; no runtime allocation) ----
__device__ __half g_bufT[N_NODES * FEAT];   // post-GEMM features (fp16)
__device__ __half g_bufH[N_NODES * FEAT];   // post-agg features (fp16)
__device__ __half g_xh[N_NODES * FEAT];     // fp16 copy of input x
__device__ int   g_deg[N_NODES];
__device__ float g_dis[N_NODES];
__device__ int   g_rowoff[N_NODES + 1];
__device__ int   g_rank[MAX_E];             // per-edge rank within its dst list
__device__ int4  g_csr4[MAX_E / 2];         // (row_byte_off, dis) pairs, 16B aligned
__device__ unsigned long long g_tilestate[SCAN_NT];

// ================= PDL helpers =================
__device__ __forceinline__ void pdl_trigger() {
#if __CUDA_ARCH__ >= 900
    cudaTriggerProgrammaticLaunchCompletion();
#endif
}
__device__ __forceinline__ void pdl_wait() {
#if __CUDA_ARCH__ >= 900
    cudaGridDependencySynchronize();
#endif
}

// ================= GEMM pieces =================
#define WROW 72

__device__ __forceinline__ uint32_t pack_h2(__half a, __half b) {
    __half2 h = __halves2half2(a, b);
    return *(uint32_t*)&h;
}
__device__ __forceinline__ void mma_f16(float* c, const uint32_t* a, uint32_t b0, uint32_t b1) {
    asm volatile(
        "mma.sync.aligned.m16n8k16.row.col.f32.f16.f16.f32 "
        "{%0,%1,%2,%3}, {%4,%5,%6,%7}, {%8,%9}, {%0,%1,%2,%3};"
        : "+f"(c[0]), "+f"(c[1]), "+f"(c[2]), "+f"(c[3])
        : "r"(a[0]), "r"(a[1]), "r"(a[2]), "r"(a[3]), "r"(b0), "r"(b1));
}
__device__ __forceinline__ void stage_W(uint32_t* Wh, const float* __restrict__ W, int tid) {
    for (int idx = tid; idx < 64 * 128; idx += 256) {
        int p = idx >> 7, n = idx & 127;
        int k = p * 2;
        float w0 = W[k * FEAT + n];
        float w1 = W[(k + 1) * FEAT + n];
        int kstep = p >> 3, q = p & 7;
        int word = n * WROW + kstep * 8 + (q & 3) * 2 + (q >> 2);
        Wh[word] = pack_h2(__float2half_rn(w0), __float2half_rn(w1));
    }
}

// stage_W runs BEFORE pdl_wait (reads only the kernel input W);
// A reads happen after the dependency sync.
__device__ __forceinline__ void gemm_body(uint32_t* Wh, const __half* __restrict__ A,
                                          const float* __restrict__ W,
                                          __half* __restrict__ C, int nrows, int tile) {
    int tid = threadIdx.x, wid = tid >> 5, lane = tid & 31;
    int g = lane >> 2, t = lane & 3;
    stage_W(Wh, W, tid);
    pdl_wait();
    __syncthreads();

    int r0 = tile * 128 + wid * 16 + g;
    int r1 = r0 + 8;
    bool v0 = r0 < nrows, v1 = r1 < nrows;

    float acc[16][4];
    #pragma unroll
    for (int n0 = 0; n0 < 16; n0++)
        #pragma unroll
        for (int j = 0; j < 4; j++) acc[n0][j] = 0.0f;

    #pragma unroll
    for (int kstep = 0; kstep < 8; kstep++) {
        int ka = kstep * 16 + 2 * t;
        uint32_t a[4];
        a[0] = v0 ? *(const uint32_t*)&A[r0 * FEAT + ka]     : 0u;
        a[1] = v1 ? *(const uint32_t*)&A[r1 * FEAT + ka]     : 0u;
        a[2] = v0 ? *(const uint32_t*)&A[r0 * FEAT + ka + 8] : 0u;
        a[3] = v1 ? *(const uint32_t*)&A[r1 * FEAT + ka + 8] : 0u;

        int bword = g * WROW + kstep * 8 + t * 2;
        #pragma unroll
        for (int n0 = 0; n0 < 16; n0++) {
            uint2 bh = *(const uint2*)&Wh[n0 * 8 * WROW + bword];
            mma_f16(acc[n0], a, bh.x, bh.y);
        }
    }

    #pragma unroll
    for (int n0 = 0; n0 < 16; n0++) {
        int col = n0 * 8 + 2 * t;
        if (v0) *(__half2*)&C[r0 * FEAT + col] = __floats2half2_rn(acc[n0][0], acc[n0][1]);
        if (v1) *(__half2*)&C[r1 * FEAT + col] = __floats2half2_rn(acc[n0][2], acc[n0][3]);
    }
}

// ================= setup bodies =================
__device__ __forceinline__ void count_body(const int* __restrict__ dst, int E, int bid) {
    int i = (bid * 256 + threadIdx.x) * 8;
    if (i + 7 < E) {
        int4 d0 = *(const int4*)&dst[i];
        int4 d1 = *(const int4*)&dst[i + 4];
        int4 r0, r1;
        r0.x = atomicAdd(&g_deg[d0.x], 1);
        r0.y = atomicAdd(&g_deg[d0.y], 1);
        r0.z = atomicAdd(&g_deg[d0.z], 1);
        r0.w = atomicAdd(&g_deg[d0.w], 1);
        r1.x = atomicAdd(&g_deg[d1.x], 1);
        r1.y = atomicAdd(&g_deg[d1.y], 1);
        r1.z = atomicAdd(&g_deg[d1.z], 1);
        r1.w = atomicAdd(&g_deg[d1.w], 1);
        *(int4*)&g_rank[i]     = r0;
        *(int4*)&g_rank[i + 4] = r1;
    } else {
        for (int j = i; j < E; j++) g_rank[j] = atomicAdd(&g_deg[dst[j]], 1);
    }
}

__device__ __forceinline__ void x2h_body(const float* __restrict__ x, __half* __restrict__ xh,
                                         int n, int bid) {
    int i = (bid * 256 + threadIdx.x) * 8;
    if (i + 7 < n) {
        float4 f0 = *(const float4*)&x[i];
        float4 f1 = *(const float4*)&x[i + 4];
        uint4 o;
        __half2 h0 = __floats2half2_rn(f0.x, f0.y);
        __half2 h1 = __floats2half2_rn(f0.z, f0.w);
        __half2 h2 = __floats2half2_rn(f1.x, f1.y);
        __half2 h3 = __floats2half2_rn(f1.z, f1.w);
        o.x = *(uint32_t*)&h0; o.y = *(uint32_t*)&h1;
        o.z = *(uint32_t*)&h2; o.w = *(uint32_t*)&h3;
        *(uint4*)&xh[i] = o;
    }
}

// fill: store (row byte offset = src*FEAT*2, dis[src]) — no atomics
__device__ __forceinline__ void fill_body(const int* __restrict__ src,
                                          const int* __restrict__ dst, int E, int bid) {
    int2* csr2 = (int2*)g_csr4;
    int i = (bid * 256 + threadIdx.x) * 8;
    if (i + 7 < E) {
        int4 s0 = *(const int4*)&src[i];
        int4 s1 = *(const int4*)&src[i + 4];
        int4 d0 = *(const int4*)&dst[i];
        int4 d1 = *(const int4*)&dst[i + 4];
        int4 r0 = *(const int4*)&g_rank[i];
        int4 r1 = *(const int4*)&g_rank[i + 4];
        float f0 = g_dis[s0.x], f1 = g_dis[s0.y], f2 = g_dis[s0.z], f3 = g_dis[s0.w];
        float f4 = g_dis[s1.x], f5 = g_dis[s1.y], f6 = g_dis[s1.z], f7 = g_dis[s1.w];
        csr2[g_rowoff[d0.x] + r0.x] = make_int2(s0.x * 256, __float_as_int(f0));
        csr2[g_rowoff[d0.y] + r0.y] = make_int2(s0.y * 256, __float_as_int(f1));
        csr2[g_rowoff[d0.z] + r0.z] = make_int2(s0.z * 256, __float_as_int(f2));
        csr2[g_rowoff[d0.w] + r0.w] = make_int2(s0.w * 256, __float_as_int(f3));
        csr2[g_rowoff[d1.x] + r1.x] = make_int2(s1.x * 256, __float_as_int(f4));
        csr2[g_rowoff[d1.y] + r1.y] = make_int2(s1.y * 256, __float_as_int(f5));
        csr2[g_rowoff[d1.z] + r1.z] = make_int2(s1.z * 256, __float_as_int(f6));
        csr2[g_rowoff[d1.w] + r1.w] = make_int2(s1.w * 256, __float_as_int(f7));
    } else {
        for (int j = i; j < E; j++) {
            int sj = src[j];
            csr2[g_rowoff[dst[j]] + g_rank[j]] = make_int2(sj * 256, __float_as_int(g_dis[sj]));
        }
    }
}

// ================= merged kernels =================
__global__ __launch_bounds__(256) void k_setup1(const int* __restrict__ dst, int E,
                                                const float* __restrict__ x,
                                                __half* __restrict__ xh, int n, int nCount) {
    pdl_trigger();
    int bid = blockIdx.x;
    if (bid < nCount) count_body(dst, E, bid);
    else              x2h_body(x, xh, n, bid - nCount);
}

__global__ __launch_bounds__(256) void k_fillgemm1(const int* __restrict__ src,
                                                   const int* __restrict__ dst, int E,
                                                   const __half* __restrict__ A,
                                                   const float* __restrict__ W,
                                                   __half* __restrict__ C,
                                                   int nrows, int ntiles) {
    __shared__ uint32_t Wh[128 * WROW];
    pdl_trigger();
    int bid = blockIdx.x;
    if (bid < ntiles) {
        gemm_body(Wh, A, W, C, nrows, bid);     // pdl_wait inside, after stage_W
    } else {
        pdl_wait();                             // rowoff/dis come from scan
        fill_body(src, dst, E, bid - ntiles);
    }
}

__global__ __launch_bounds__(256) void k_gemm_h(const __half* __restrict__ A,
                                                const float* __restrict__ W,
                                                __half* __restrict__ C, int nrows) {
    __shared__ uint32_t Wh[128 * WROW];
    pdl_trigger();
    gemm_body(Wh, A, W, C, nrows, blockIdx.x);
}

// ================= scan =================
__global__ __launch_bounds__(1024) void k_scan_dl() {
    __shared__ int sh_w[32];
    __shared__ unsigned int sh_prefix;
    pdl_trigger();
    pdl_wait();
    int tid = threadIdx.x, lane = tid & 31, wid = tid >> 5;
    int tile = blockIdx.x;
    int i0 = tile * SCAN_TILE + tid * 4;

    int4 v = make_int4(0, 0, 0, 0);
    if (i0 < N_NODES) {
        v = *(const int4*)&g_deg[i0];
        float4 d;
        d.x = rsqrtf((float)(v.x + 1));
        d.y = rsqrtf((float)(v.y + 1));
        d.z = rsqrtf((float)(v.z + 1));
        d.w = rsqrtf((float)(v.w + 1));
        *(float4*)&g_dis[i0] = d;
    }
    int t0 = v.x, t1 = t0 + v.y, t2 = t1 + v.z, t3 = t2 + v.w;
    int sc = t3;
    #pragma unroll
    for (int d = 1; d < 32; d <<= 1) {
        int t = __shfl_up_sync(0xffffffffu, sc, d);
        if (lane >= d) sc += t;
    }
    if (lane == 31) sh_w[wid] = sc;
    __syncthreads();
    if (wid == 0) {
        int ws = sh_w[lane];
        #pragma unroll
        for (int d = 1; d < 32; d <<= 1) {
            int t = __shfl_up_sync(0xffffffffu, ws, d);
            if (lane >= d) ws += t;
        }
        sh_w[lane] = ws;
    }
    __syncthreads();
    int total = sh_w[31];
    int thr_excl = (wid ? sh_w[wid - 1] : 0) + sc - t3;

    if (tid == 0) {
        unsigned long long st = ((tile == 0) ? (2ULL << 32) : (1ULL << 32)) | (unsigned)total;
        atomicExch(&g_tilestate[tile], st);
    }
    if (wid == 0) {
        unsigned int prefix = 0;
        if (tile > 0) {
            bool have = lane < tile;
            unsigned long long s = 0;
            if (have) {
                do { s = *(volatile unsigned long long*)&g_tilestate[tile - 1 - lane]; }
                while ((unsigned)(s >> 32) == 0u);
            }
            unsigned flag = (unsigned)(s >> 32);
            unsigned mask = __ballot_sync(0xffffffffu, have && flag == 2u);
            int firstInc = __ffs(mask) - 1;   // exists: tile 0 is always INCLUSIVE
            unsigned contrib = (have && lane <= firstInc) ? (unsigned)s : 0u;
            #pragma unroll
            for (int d = 16; d; d >>= 1) contrib += __shfl_xor_sync(0xffffffffu, contrib, d);
            prefix = contrib;
            if (lane == 0)
                atomicExch(&g_tilestate[tile], (2ULL << 32) | (unsigned)(prefix + (unsigned)total));
        }
        if (lane == 0) sh_prefix = prefix;
    }
    __syncthreads();
    int base = (int)sh_prefix + thr_excl;
    if (i0 < N_NODES) {
        int4 o = make_int4(base, base + t0, base + t1, base + t2);
        *(int4*)&g_rowoff[i0] = o;
    }
    if (tile == SCAN_NT - 1 && tid == 0) g_rowoff[N_NODES] = (int)sh_prefix + total;
}

// ================= aggregation v4: premult offsets + int4 CSR, flat loop ==
__device__ __forceinline__ float elu1(float v) {
    return v > 0.0f ? v : (__expf(v) - 1.0f);   // fast ELU via MUFU
}

__device__ __forceinline__ uint2 ld_row_off(const char* __restrict__ Tl, int off) {
    return *(const uint2*)(Tl + off);
}
__device__ __forceinline__ void acc_row(float4& acc, uint2 u, float w) {
    __half2 h0 = *(__half2*)&u.x;
    __half2 h1 = *(__half2*)&u.y;
    float2 f0 = __half22float2(h0);
    float2 f1 = __half22float2(h1);
    acc.x = fmaf(w, f0.x, acc.x);
    acc.y = fmaf(w, f0.y, acc.y);
    acc.z = fmaf(w, f1.x, acc.z);
    acc.w = fmaf(w, f1.y, acc.w);
}

template<int FUSE_FINAL>
__global__ __launch_bounds__(256) void k_agg_t(const __half* __restrict__ T,
                                               const float* __restrict__ bias,
                                               __half* __restrict__ Hout,
                                               const float* __restrict__ Wl,
                                               const float* __restrict__ bl,
                                               float* __restrict__ out) {
    pdl_trigger();
    pdl_wait();
    const int2* __restrict__ csr2 = (const int2*)g_csr4;
    int warp = (int)((blockIdx.x * blockDim.x + threadIdx.x) >> 5);
    int lane = threadIdx.x & 31;
    if (warp >= N_NODES) return;
    int node = warp;
    float dd = g_dis[node];
    const char* Tl = (const char*)(T + lane * 4);   // lane's column base

    float4 acc;
    {
        uint2 u = ld_row_off(Tl, node * 256);
        __half2 h0 = *(__half2*)&u.x;
        __half2 h1 = *(__half2*)&u.y;
        float2 f0 = __half22float2(h0);
        float2 f1 = __half22float2(h1);
        float ws = dd * dd;
        acc = make_float4(ws * f0.x, ws * f0.y, ws * f1.x, ws * f1.y);
    }

    int e   = g_rowoff[node];
    int end = g_rowoff[node + 1];

    if (e < end && (e & 1)) {           // align to int4 boundary
        int2 p = csr2[e];
        acc_row(acc, ld_row_off(Tl, p.x), __int_as_float(p.y) * dd);
        e++;
    }
    for (; e + 3 < end; e += 4) {       // 4 edges: 2 LDG.128 csr + 4 row LDG
        int4 pa = *(const int4*)&csr2[e];
        int4 pb = *(const int4*)&csr2[e + 2];
        uint2 r0 = ld_row_off(Tl, pa.x);
        uint2 r1 = ld_row_off(Tl, pa.z);
        uint2 r2 = ld_row_off(Tl, pb.x);
        uint2 r3 = ld_row_off(Tl, pb.z);
        acc_row(acc, r0, __int_as_float(pa.y) * dd);
        acc_row(acc, r1, __int_as_float(pa.w) * dd);
        acc_row(acc, r2, __int_as_float(pb.y) * dd);
        acc_row(acc, r3, __int_as_float(pb.w) * dd);
    }
    for (; e < end; e++) {              // tail 0-3 edges
        int2 p = csr2[e];
        acc_row(acc, ld_row_off(Tl, p.x), __int_as_float(p.y) * dd);
    }

    float4 b = *(const float4*)&bias[lane * 4];
    float4 r;
    r.x = elu1(acc.x + b.x);
    r.y = elu1(acc.y + b.y);
    r.z = elu1(acc.z + b.z);
    r.w = elu1(acc.w + b.w);

    if (FUSE_FINAL) {
        float4 w = *(const float4*)&Wl[lane * 4];
        float s = r.x * w.x + r.y * w.y + r.z * w.z + r.w * w.w;
        #pragma unroll
        for (int d = 16; d; d >>= 1) s += __shfl_xor_sync(0xffffffffu, s, d);
        if (lane == 0) out[node] = s + bl[0];
    } else {
        uint2 st;
        __half2 h0 = __floats2half2_rn(r.x, r.y);
        __half2 h1 = __floats2half2_rn(r.z, r.w);
        st.x = *(uint32_t*)&h0;
        st.y = *(uint32_t*)&h1;
        *(uint2*)&Hout[node * FEAT + lane * 4] = st;
    }
}

// ================= launch =================
extern "C" void kernel_launch(void* const* d_in, const int* in_sizes, int n_in,
                              void* d_out, int out_size) {
    const float* x  = (const float*)d_in[0];
    const float* Ws = (const float*)d_in[1];
    const float* bs = (const float*)d_in[2];
    const float* Wl = (const float*)d_in[3];
    const float* bl = (const float*)d_in[4];
    const int*   ei = (const int*)d_in[5];
    const int E = in_sizes[5] / 2;
    const int* src = ei;
    const int* dst = ei + E;
    float* out = (float*)d_out;

    __half *hbuf = nullptr, *tbuf = nullptr, *xh = nullptr;
    void *degp = nullptr, *tsp = nullptr;
    cudaGetSymbolAddress((void**)&hbuf, g_bufH);
    cudaGetSymbolAddress((void**)&tbuf, g_bufT);
    cudaGetSymbolAddress((void**)&xh, g_xh);
    cudaGetSymbolAddress(&degp, g_deg);
    cudaGetSymbolAddress(&tsp, g_tilestate);

    cudaMemsetAsync(degp, 0, N_NODES * sizeof(int), 0);
    cudaMemsetAsync(tsp, 0, SCAN_NT * sizeof(unsigned long long), 0);

    const int nX = N_NODES * FEAT;
    const int nCount = (E / 8 + 255) / 256;          // 391
    const int nX2h   = (nX / 8 + 255) / 256;         // 3125
    const int ntiles = (N_NODES + 127) / 128;        // 391
    const int nFill  = (E / 8 + 255) / 256;          // 391
    const int nagg   = (N_NODES + 7) / 8;

    // PDL launch config helper
    cudaLaunchAttribute pdlAttr[1];
    pdlAttr[0].id = cudaLaunchAttributeProgrammaticStreamSerialization;
    pdlAttr[0].val.programmaticStreamSerializationAllowed = 1;
    auto mkcfg = [&](int grid, int block) {
        cudaLaunchConfig_t cfg = {};
        cfg.gridDim = dim3(grid);
        cfg.blockDim = dim3(block);
        cfg.dynamicSmemBytes = 0;
        cfg.stream = 0;
        cfg.attrs = pdlAttr;
        cfg.numAttrs = 1;
        return cfg;
    };

    // setup1 (normal launch; predecessor is memset)
    k_setup1<<<nCount + nX2h, 256>>>(dst, E, x, xh, nX, nCount);

    {   // scan (PDL after setup1)
        cudaLaunchConfig_t cfg = mkcfg(SCAN_NT, 1024);
        cudaLaunchKernelEx(&cfg, k_scan_dl);
    }
    {   // fill + gemm1 (PDL after scan; gemm1 stages W pre-sync)
        cudaLaunchConfig_t cfg = mkcfg(ntiles + nFill, 256);
        cudaLaunchKernelEx(&cfg, k_fillgemm1, src, dst, E,
                           (const __half*)xh, Ws, tbuf, (int)N_NODES, ntiles);
    }
    {   // agg1
        cudaLaunchConfig_t cfg = mkcfg(nagg, 256);
        cudaLaunchKernelEx(&cfg, k_agg_t<0>, (const __half*)tbuf, bs, hbuf,
                           (const float*)nullptr, (const float*)nullptr, (float*)nullptr);
    }
    {   // gemm2
        cudaLaunchConfig_t cfg = mkcfg(ntiles, 256);
        cudaLaunchKernelEx(&cfg, k_gemm_h, (const __half*)hbuf, Ws + FEAT * FEAT,
                           tbuf, (int)N_NODES);
    }
    {   // agg2
        cudaLaunchConfig_t cfg = mkcfg(nagg, 256);
        cudaLaunchKernelEx(&cfg, k_agg_t<0>, (const __half*)tbuf, bs + FEAT, hbuf,
                           (const float*)nullptr, (const float*)nullptr, (float*)nullptr);
    }
    {   // gemm3
        cudaLaunchConfig_t cfg = mkcfg(ntiles, 256);
        cudaLaunchKernelEx(&cfg, k_gemm_h, (const __half*)hbuf, Ws + 2 * FEAT * FEAT,
                           tbuf, (int)N_NODES);
    }
    {   // agg3 + fused final projection
        cudaLaunchConfig_t cfg = mkcfg(nagg, 256);
        cudaLaunchKernelEx(&cfg, k_agg_t<1>, (const __half*)tbuf, bs + 2 * FEAT,
                           (__half*)nullptr, Wl, bl, out);
    }
}